// round 1
// baseline (speedup 1.0000x reference)
#include <cuda_runtime.h>
#include <cuda_bf16.h>
#include <cstdint>

// EdgeDecoder: out[e] = relu(z_user[row[e]] @ W1u + z_item[col[e]] @ W1i + b1) @ W2 + b2
// H = 128.
// Strategy: precompute per-node projections (two small GEMMs, 2.46e9 FMAs total),
// then a gather+relu+dot edge kernel (L2-bandwidth bound).

#define H 128
#define N_USER_MAX 100000
#define N_ITEM_MAX 50000

// Scratch (allocation-free): projected embeddings.
__device__ float g_uproj[(size_t)N_USER_MAX * H];   // 51.2 MB
__device__ float g_iproj[(size_t)N_ITEM_MAX * H];   // 25.6 MB

// ---------------------------------------------------------------------------
// GEMM: P[M x 128] = Z[M x 128] @ W[128 x 128]   (all row-major, fp32)
// Block tile: 64 rows x 128 cols, K-tiled by 32. 256 threads, each computes 4x8.
// ---------------------------------------------------------------------------
#define TILE_M 64
#define TILE_K 32

__global__ __launch_bounds__(256) void proj_kernel(
    const float* __restrict__ Z,
    const float* __restrict__ W,     // 128x128 row-major (W1 offset applied by caller)
    float* __restrict__ P,
    int M)
{
    __shared__ float As[TILE_M][TILE_K + 1];   // +1 pad: conflict-free column reads
    __shared__ float Ws[TILE_K][H + 4];

    const int block_m = blockIdx.x * TILE_M;
    const int tx = threadIdx.x;          // 0..255
    const int rm = tx >> 4;              // 0..15  -> 4 rows each
    const int cn = tx & 15;              // 0..15  -> 8 cols each

    float acc[4][8];
    #pragma unroll
    for (int i = 0; i < 4; i++)
        #pragma unroll
        for (int j = 0; j < 8; j++) acc[i][j] = 0.f;

    for (int k0 = 0; k0 < H; k0 += TILE_K) {
        // Load A tile: 64x32 floats, 8 per thread
        #pragma unroll
        for (int i = tx; i < TILE_M * TILE_K; i += 256) {
            int r = i / TILE_K, c = i % TILE_K;
            int gr = block_m + r;
            As[r][c] = (gr < M) ? Z[(size_t)gr * H + k0 + c] : 0.f;
        }
        // Load W tile: 32x128 floats, 16 per thread (vectorize as float4)
        #pragma unroll
        for (int i = tx; i < TILE_K * (H / 4); i += 256) {
            int r = i / (H / 4), c4 = i % (H / 4);
            float4 v = reinterpret_cast<const float4*>(W + (size_t)(k0 + r) * H)[c4];
            Ws[r][c4 * 4 + 0] = v.x;
            Ws[r][c4 * 4 + 1] = v.y;
            Ws[r][c4 * 4 + 2] = v.z;
            Ws[r][c4 * 4 + 3] = v.w;
        }
        __syncthreads();

        #pragma unroll
        for (int k = 0; k < TILE_K; k++) {
            float a[4], b[8];
            #pragma unroll
            for (int i = 0; i < 4; i++) a[i] = As[rm * 4 + i][k];
            #pragma unroll
            for (int j = 0; j < 8; j++) b[j] = Ws[k][cn * 8 + j];
            #pragma unroll
            for (int i = 0; i < 4; i++)
                #pragma unroll
                for (int j = 0; j < 8; j++)
                    acc[i][j] = fmaf(a[i], b[j], acc[i][j]);
        }
        __syncthreads();
    }

    // Store 4 rows x 8 cols, vectorized float4 x2 per row
    #pragma unroll
    for (int i = 0; i < 4; i++) {
        int gr = block_m + rm * 4 + i;
        if (gr < M) {
            float4* dst = reinterpret_cast<float4*>(P + (size_t)gr * H + cn * 8);
            dst[0] = make_float4(acc[i][0], acc[i][1], acc[i][2], acc[i][3]);
            dst[1] = make_float4(acc[i][4], acc[i][5], acc[i][6], acc[i][7]);
        }
    }
}

// ---------------------------------------------------------------------------
// Edge kernel: one warp per edge.
//   h = relu(uproj[row[e]] + iproj[col[e]] + b1); out[e] = h . W2 + b2
// Each lane handles 4 consecutive floats (float4): 32 lanes x 4 = 128 = H.
// Gathers are fully coalesced 512B blocks; mostly L2-resident (77MB < 126MB).
// ---------------------------------------------------------------------------
__global__ __launch_bounds__(256) void edge_kernel(
    const int* __restrict__ row,
    const int* __restrict__ col,
    const float* __restrict__ b1,
    const float* __restrict__ W2,
    const float* __restrict__ b2,
    float* __restrict__ out,
    int E)
{
    const int warp = (blockIdx.x * blockDim.x + threadIdx.x) >> 5;
    const int lane = threadIdx.x & 31;
    if (warp >= E) return;

    const int r = row[warp];
    const int c = col[warp];

    float4 u  = reinterpret_cast<const float4*>(g_uproj + (size_t)r * H)[lane];
    float4 v  = reinterpret_cast<const float4*>(g_iproj + (size_t)c * H)[lane];
    float4 bb = reinterpret_cast<const float4*>(b1)[lane];
    float4 w  = reinterpret_cast<const float4*>(W2)[lane];

    float s = fmaxf(u.x + v.x + bb.x, 0.f) * w.x
            + fmaxf(u.y + v.y + bb.y, 0.f) * w.y
            + fmaxf(u.z + v.z + bb.z, 0.f) * w.z
            + fmaxf(u.w + v.w + bb.w, 0.f) * w.w;

    // Warp reduction
    #pragma unroll
    for (int o = 16; o > 0; o >>= 1)
        s += __shfl_xor_sync(0xffffffffu, s, o);

    if (lane == 0) out[warp] = s + b2[0];
}

// ---------------------------------------------------------------------------
// Launch. Input order (metadata): z_user, z_item, row, col, W1, b1, W2, b2
// ---------------------------------------------------------------------------
extern "C" void kernel_launch(void* const* d_in, const int* in_sizes, int n_in,
                              void* d_out, int out_size)
{
    const float* z_user = (const float*)d_in[0];
    const float* z_item = (const float*)d_in[1];
    const int*   row    = (const int*)  d_in[2];
    const int*   col    = (const int*)  d_in[3];
    const float* W1     = (const float*)d_in[4];   // (2H, H) row-major
    const float* b1     = (const float*)d_in[5];
    const float* W2     = (const float*)d_in[6];   // (H, 1) == 128 floats
    const float* b2     = (const float*)d_in[7];

    const int n_user = in_sizes[0] / H;
    const int n_item = in_sizes[1] / H;
    const int E      = in_sizes[2];

    float* uproj;
    float* iproj;
    cudaGetSymbolAddress((void**)&uproj, g_uproj);
    cudaGetSymbolAddress((void**)&iproj, g_iproj);

    // Projection GEMMs: W1u = W1[0:128], W1i = W1[128:256]
    {
        dim3 grid_u((n_user + TILE_M - 1) / TILE_M);
        proj_kernel<<<grid_u, 256>>>(z_user, W1, uproj, n_user);
        dim3 grid_i((n_item + TILE_M - 1) / TILE_M);
        proj_kernel<<<grid_i, 256>>>(z_item, W1 + (size_t)H * H, iproj, n_item);
    }

    // Edge gather + relu + dot: 8 warps/block
    {
        int warps_per_block = 8;
        int blocks = (E + warps_per_block - 1) / warps_per_block;
        edge_kernel<<<blocks, warps_per_block * 32>>>(row, col, b1, W2, b2,
                                                      (float*)d_out, E);
    }
}

// round 5
// speedup vs baseline: 1.7185x; 1.7185x over previous
#include <cuda_runtime.h>
#include <cuda_bf16.h>
#include <cstdint>

// EdgeDecoder: out[e] = relu(z_user[row[e]] @ W1u + z_item[col[e]] @ W1i + b1) @ W2 + b2
// H = 128.
// R4 (resubmit of R3; broker timeouts R2-R4):
//     fused projection GEMM using packed fma.rn.f32x2 (2 FMAs/issue slot on sm_103a),
//     128x128 block tile / 8x8 thread tile, double-buffered smem.
//     Edge kernel: 4 edges per warp (8 gathers in flight), int4 index loads.

#define H 128
#define N_USER_MAX 100000
#define N_ITEM_MAX 50000

__device__ float g_uproj[(size_t)N_USER_MAX * H];   // 51.2 MB
__device__ float g_iproj[(size_t)N_ITEM_MAX * H];   // 25.6 MB

#define PTILE_M 128
#define PTILE_K 16
#define AS_LD (PTILE_M + 4)   // 132 floats/row
#define WS_LD (H + 4)         // 132

__device__ __forceinline__ unsigned long long pack_dup(float a) {
    unsigned long long r;
    asm("mov.b64 %0, {%1, %1};" : "=l"(r) : "r"(__float_as_uint(a)));
    return r;
}
__device__ __forceinline__ void fma2(unsigned long long& d,
                                     unsigned long long a,
                                     unsigned long long b) {
    asm("fma.rn.f32x2 %0, %1, %2, %0;" : "+l"(d) : "l"(a), "l"(b));
}
__device__ __forceinline__ void unpack2(unsigned long long v, float& lo, float& hi) {
    unsigned int l, h;
    asm("mov.b64 {%0, %1}, %2;" : "=r"(l), "=r"(h) : "l"(v));
    lo = __uint_as_float(l);
    hi = __uint_as_float(h);
}

// ---------------------------------------------------------------------------
// Fused projection GEMM. Block b < blocks_u handles z_user rows with W1u;
// otherwise z_item rows with W1i. P[M x 128] = Z[M x 128] @ W[128 x 128].
// 256 threads; thread computes an 8x8 output tile via f32x2 packed FMAs.
// ---------------------------------------------------------------------------
__global__ __launch_bounds__(256, 2) void proj_kernel(
    const float* __restrict__ Zu, const float* __restrict__ Zi,
    const float* __restrict__ W1,
    float* __restrict__ Pu, float* __restrict__ Pi,
    int Mu, int Mi, int blocks_u)
{
    __shared__ float As[2][PTILE_K][AS_LD];
    __shared__ float Ws[2][PTILE_K][WS_LD];

    const float* Z; const float* W; float* P; int M; int m0;
    if ((int)blockIdx.x < blocks_u) {
        Z = Zu; W = W1;             P = Pu; M = Mu; m0 = blockIdx.x * PTILE_M;
    } else {
        Z = Zi; W = W1 + H * H;     P = Pi; M = Mi; m0 = (blockIdx.x - blocks_u) * PTILE_M;
    }

    const int tid = threadIdx.x;          // 0..255
    const int ty  = tid >> 4;             // 0..15 -> 8 rows each
    const int tx  = tid & 15;             // 0..15 -> 8 cols each

    // A-tile load mapping: 128 rows x 16 k = 512 float4; 2 per thread.
    const int af0 = tid * 2;              // float4 index 0..511
    const int ar0 = af0 >> 2, ac0 = (af0 & 3) * 4;       // row, k-offset
    const int ar1 = (af0 + 1) >> 2, ac1 = ((af0 + 1) & 3) * 4;
    // W-tile load mapping: 16 k x 128 cols = 512 float4; 2 per thread.
    const int wr0 = (tid * 2) >> 5, wc0 = ((tid * 2) & 31) * 4;
    const int wr1 = (tid * 2 + 1) >> 5, wc1 = ((tid * 2 + 1) & 31) * 4;

    unsigned long long acc2[8][4];
    #pragma unroll
    for (int i = 0; i < 8; i++)
        #pragma unroll
        for (int p = 0; p < 4; p++) acc2[i][p] = 0ull;

    float4 pa0, pa1, pw0, pw1;   // prefetch registers

    // --- load tile 0 ---
    {
        const int k0 = 0;
        pa0 = (m0 + ar0 < M) ? *reinterpret_cast<const float4*>(Z + (size_t)(m0 + ar0) * H + k0 + ac0)
                             : make_float4(0.f, 0.f, 0.f, 0.f);
        pa1 = (m0 + ar1 < M) ? *reinterpret_cast<const float4*>(Z + (size_t)(m0 + ar1) * H + k0 + ac1)
                             : make_float4(0.f, 0.f, 0.f, 0.f);
        pw0 = *reinterpret_cast<const float4*>(W + (size_t)(k0 + wr0) * H + wc0);
        pw1 = *reinterpret_cast<const float4*>(W + (size_t)(k0 + wr1) * H + wc1);
        // store (transpose A into [k][row])
        As[0][ac0 + 0][ar0] = pa0.x; As[0][ac0 + 1][ar0] = pa0.y;
        As[0][ac0 + 2][ar0] = pa0.z; As[0][ac0 + 3][ar0] = pa0.w;
        As[0][ac1 + 0][ar1] = pa1.x; As[0][ac1 + 1][ar1] = pa1.y;
        As[0][ac1 + 2][ar1] = pa1.z; As[0][ac1 + 3][ar1] = pa1.w;
        *reinterpret_cast<float4*>(&Ws[0][wr0][wc0]) = pw0;
        *reinterpret_cast<float4*>(&Ws[0][wr1][wc1]) = pw1;
    }

    #pragma unroll
    for (int t = 0; t < H / PTILE_K; t++) {
        __syncthreads();
        const int cur = t & 1;

        if (t < H / PTILE_K - 1) {
            const int k0 = (t + 1) * PTILE_K;
            pa0 = (m0 + ar0 < M) ? *reinterpret_cast<const float4*>(Z + (size_t)(m0 + ar0) * H + k0 + ac0)
                                 : make_float4(0.f, 0.f, 0.f, 0.f);
            pa1 = (m0 + ar1 < M) ? *reinterpret_cast<const float4*>(Z + (size_t)(m0 + ar1) * H + k0 + ac1)
                                 : make_float4(0.f, 0.f, 0.f, 0.f);
            pw0 = *reinterpret_cast<const float4*>(W + (size_t)(k0 + wr0) * H + wc0);
            pw1 = *reinterpret_cast<const float4*>(W + (size_t)(k0 + wr1) * H + wc1);
        }

        #pragma unroll
        for (int k = 0; k < PTILE_K; k++) {
            float4 aLo = *reinterpret_cast<const float4*>(&As[cur][k][ty * 8]);
            float4 aHi = *reinterpret_cast<const float4*>(&As[cur][k][ty * 8 + 4]);
            ulonglong2 b01 = *reinterpret_cast<const ulonglong2*>(&Ws[cur][k][tx * 8]);
            ulonglong2 b23 = *reinterpret_cast<const ulonglong2*>(&Ws[cur][k][tx * 8 + 4]);
            float a[8] = {aLo.x, aLo.y, aLo.z, aLo.w, aHi.x, aHi.y, aHi.z, aHi.w};
            #pragma unroll
            for (int i = 0; i < 8; i++) {
                unsigned long long av = pack_dup(a[i]);
                fma2(acc2[i][0], av, b01.x);
                fma2(acc2[i][1], av, b01.y);
                fma2(acc2[i][2], av, b23.x);
                fma2(acc2[i][3], av, b23.y);
            }
        }

        if (t < H / PTILE_K - 1) {
            __syncthreads();
            const int nxt = (t + 1) & 1;
            As[nxt][ac0 + 0][ar0] = pa0.x; As[nxt][ac0 + 1][ar0] = pa0.y;
            As[nxt][ac0 + 2][ar0] = pa0.z; As[nxt][ac0 + 3][ar0] = pa0.w;
            As[nxt][ac1 + 0][ar1] = pa1.x; As[nxt][ac1 + 1][ar1] = pa1.y;
            As[nxt][ac1 + 2][ar1] = pa1.z; As[nxt][ac1 + 3][ar1] = pa1.w;
            *reinterpret_cast<float4*>(&Ws[nxt][wr0][wc0]) = pw0;
            *reinterpret_cast<float4*>(&Ws[nxt][wr1][wc1]) = pw1;
        }
    }

    // --- store 8x8 tile ---
    #pragma unroll
    for (int i = 0; i < 8; i++) {
        int gr = m0 + ty * 8 + i;
        if (gr < M) {
            float o[8];
            #pragma unroll
            for (int p = 0; p < 4; p++) unpack2(acc2[i][p], o[2 * p], o[2 * p + 1]);
            float4* dst = reinterpret_cast<float4*>(P + (size_t)gr * H + tx * 8);
            dst[0] = make_float4(o[0], o[1], o[2], o[3]);
            dst[1] = make_float4(o[4], o[5], o[6], o[7]);
        }
    }
}

// ---------------------------------------------------------------------------
// Edge kernel: one warp per FOUR edges (8 gathers in flight per warp).
//   h = relu(uproj[r] + iproj[c] + b1); out[e] = h . W2 + b2
// Lane handles 4 consecutive floats (float4). Gathers are coalesced 512B rows,
// mostly L2-resident (77MB projections < 126MB L2). Tail edges handled by a
// scalar path (duplicate last index; masked store).
// ---------------------------------------------------------------------------
#define EDGES_PER_WARP 4

__global__ __launch_bounds__(256) void edge_kernel(
    const int* __restrict__ row,
    const int* __restrict__ col,
    const float* __restrict__ b1,
    const float* __restrict__ W2,
    const float* __restrict__ b2,
    float* __restrict__ out,
    int E)
{
    const int warp = (blockIdx.x * blockDim.x + threadIdx.x) >> 5;
    const int lane = threadIdx.x & 31;
    const int e0 = warp * EDGES_PER_WARP;
    if (e0 >= E) return;

    float4 bb = reinterpret_cast<const float4*>(b1)[lane];
    float4 w  = reinterpret_cast<const float4*>(W2)[lane];

    int r[EDGES_PER_WARP], c[EDGES_PER_WARP];
    if (e0 + EDGES_PER_WARP <= E) {
        int4 rp = *reinterpret_cast<const int4*>(row + e0);
        int4 cp = *reinterpret_cast<const int4*>(col + e0);
        r[0] = rp.x; r[1] = rp.y; r[2] = rp.z; r[3] = rp.w;
        c[0] = cp.x; c[1] = cp.y; c[2] = cp.z; c[3] = cp.w;
    } else {
        #pragma unroll
        for (int i = 0; i < EDGES_PER_WARP; i++) {
            int e = (e0 + i < E) ? e0 + i : E - 1;
            r[i] = row[e]; c[i] = col[e];
        }
    }

    float4 u[EDGES_PER_WARP], v[EDGES_PER_WARP];
    #pragma unroll
    for (int i = 0; i < EDGES_PER_WARP; i++)
        u[i] = reinterpret_cast<const float4*>(g_uproj + (size_t)r[i] * H)[lane];
    #pragma unroll
    for (int i = 0; i < EDGES_PER_WARP; i++)
        v[i] = reinterpret_cast<const float4*>(g_iproj + (size_t)c[i] * H)[lane];

    float s[EDGES_PER_WARP];
    #pragma unroll
    for (int i = 0; i < EDGES_PER_WARP; i++) {
        s[i] = fmaxf(u[i].x + v[i].x + bb.x, 0.f) * w.x
             + fmaxf(u[i].y + v[i].y + bb.y, 0.f) * w.y
             + fmaxf(u[i].z + v[i].z + bb.z, 0.f) * w.z
             + fmaxf(u[i].w + v[i].w + bb.w, 0.f) * w.w;
    }

    #pragma unroll
    for (int o = 16; o > 0; o >>= 1) {
        #pragma unroll
        for (int i = 0; i < EDGES_PER_WARP; i++)
            s[i] += __shfl_xor_sync(0xffffffffu, s[i], o);
    }

    if (lane == 0) {
        float bias = b2[0];
        #pragma unroll
        for (int i = 0; i < EDGES_PER_WARP; i++)
            if (e0 + i < E) out[e0 + i] = s[i] + bias;
    }
}

// ---------------------------------------------------------------------------
// Launch. Input order (metadata): z_user, z_item, row, col, W1, b1, W2, b2
// ---------------------------------------------------------------------------
extern "C" void kernel_launch(void* const* d_in, const int* in_sizes, int n_in,
                              void* d_out, int out_size)
{
    const float* z_user = (const float*)d_in[0];
    const float* z_item = (const float*)d_in[1];
    const int*   row    = (const int*)  d_in[2];
    const int*   col    = (const int*)  d_in[3];
    const float* W1     = (const float*)d_in[4];   // (2H, H) row-major
    const float* b1     = (const float*)d_in[5];
    const float* W2     = (const float*)d_in[6];   // (H, 1) == 128 floats
    const float* b2     = (const float*)d_in[7];

    const int n_user = in_sizes[0] / H;
    const int n_item = in_sizes[1] / H;
    const int E      = in_sizes[2];

    float* uproj;
    float* iproj;
    cudaGetSymbolAddress((void**)&uproj, g_uproj);
    cudaGetSymbolAddress((void**)&iproj, g_iproj);

    // Fused projection GEMM
    {
        int blocks_u = (n_user + PTILE_M - 1) / PTILE_M;
        int blocks_i = (n_item + PTILE_M - 1) / PTILE_M;
        proj_kernel<<<blocks_u + blocks_i, 256>>>(z_user, z_item, W1,
                                                  uproj, iproj,
                                                  n_user, n_item, blocks_u);
    }

    // Edge gather + relu + dot: 8 warps/block, 4 edges/warp
    {
        int warps = (E + EDGES_PER_WARP - 1) / EDGES_PER_WARP;
        int blocks = (warps + 7) / 8;
        edge_kernel<<<blocks, 256>>>(row, col, b1, W2, b2, (float*)d_out, E);
    }
}